// round 13
// baseline (speedup 1.0000x reference)
#include <cuda_runtime.h>
#include <cuda_fp16.h>
#include <cstdint>

#define NB   32
#define SS   2048
#define CI   256
#define CO   256
#define KW   16
#define TOUT 2033

#define MT   128
#define NT   128
#define ICH  64
#define NIC  (CI / ICH)    // 4
#define NITER (NIC * KW)   // 64
#define AROWS 143
#define AUNITS (AROWS * 16)   // 2288 float4 conversion units per A chunk

#define ABUF   18432                 // 144 rows * 128B
#define A_OFF  1024
#define B_OFF  (A_OFF + 2 * ABUF)    // 37888
#define BSTG   16384                 // 128 rows * 128B
#define NSTG   4
#define SMEM_TOTAL (B_OFF + NSTG * BSTG)   // 103424

#define B_BYTES (128 * 128)          // 16384

// mbarriers in smem: B stages at +0..+24
#define MB_B(s) (sb + 8u * (uint32_t)(s))

// ---------------- device scratch (pre-swizzled, tile-contiguous) ----------------
__device__ __half g_wt[(size_t)KW * NIC * CO * 64];     // [k][ic][o][row 128B, SW128]

// ---------------- helpers ----------------
__device__ __forceinline__ uint32_t s2u(const void* p) {
    uint32_t a;
    asm("{ .reg .u64 t; cvta.to.shared.u64 t, %1; cvt.u32.u64 %0, t; }"
        : "=r"(a) : "l"(p));
    return a;
}
__device__ __forceinline__ void mbar_init(uint32_t a) {
    asm volatile("mbarrier.init.shared.b64 [%0], 1;" :: "r"(a) : "memory");
}
__device__ __forceinline__ void mbar_expect(uint32_t a, uint32_t bytes) {
    asm volatile("mbarrier.arrive.expect_tx.shared.b64 _, [%0], %1;"
                 :: "r"(a), "r"(bytes) : "memory");
}
__device__ __forceinline__ void bulk_g2s(uint32_t dst, const void* src,
                                         uint32_t bytes, uint32_t mbar) {
    asm volatile(
        "cp.async.bulk.shared::cluster.global.mbarrier::complete_tx::bytes "
        "[%0], [%1], %2, [%3];"
        :: "r"(dst), "l"(src), "r"(bytes), "r"(mbar) : "memory");
}
__device__ __forceinline__ void mbar_wait(uint32_t a, uint32_t parity) {
    asm volatile(
        "{\n\t.reg .pred P;\n\t"
        "WL_%=:\n\t"
        "mbarrier.try_wait.parity.acquire.cta.shared::cta.b64 P, [%0], %1, 0x989680;\n\t"
        "@P bra.uni WD_%=;\n\t"
        "bra.uni WL_%=;\n\t"
        "WD_%=:\n\t}"
        :: "r"(a), "r"(parity) : "memory");
}
__device__ __forceinline__ void ldm_x4(uint32_t* r, uint32_t a) {
    asm volatile("ldmatrix.sync.aligned.m8n8.x4.shared.b16 {%0,%1,%2,%3}, [%4];"
                 : "=r"(r[0]), "=r"(r[1]), "=r"(r[2]), "=r"(r[3]) : "r"(a));
}
__device__ __forceinline__ void mma16816(float* c, const uint32_t* a, const uint32_t* b) {
    asm volatile(
        "mma.sync.aligned.m16n8k16.row.col.f32.f16.f16.f32 "
        "{%0,%1,%2,%3}, {%4,%5,%6,%7}, {%8,%9}, {%0,%1,%2,%3};"
        : "+f"(c[0]), "+f"(c[1]), "+f"(c[2]), "+f"(c[3])
        : "r"(a[0]), "r"(a[1]), "r"(a[2]), "r"(a[3]), "r"(b[0]), "r"(b[1]));
}

// one float4 of x -> 4 halves into SW128 A buffer
__device__ __forceinline__ void conv_A_unit(uint32_t abase, const float* xb,
                                            int t0, int icn, int u) {
    int row = u >> 4, seg = u & 15;
    int t = t0 + row;
    float4 v = make_float4(0.f, 0.f, 0.f, 0.f);
    if (t < SS)
        v = *reinterpret_cast<const float4*>(xb + (size_t)t * CI + icn * ICH + seg * 4);
    __half2 h01(__float2half(v.x), __float2half(v.y));
    __half2 h23(__float2half(v.z), __float2half(v.w));
    uint32_t cb = ((uint32_t)(seg * 8)) ^ (((uint32_t)row & 7) << 4);
    uint32_t d = abase + (uint32_t)row * 128 + cb;
    asm volatile("st.shared.v2.u32 [%0], {%1,%2};"
                 :: "r"(d), "r"(*(uint32_t*)&h01), "r"(*(uint32_t*)&h23));
}

// ---------------- w prep kernel (writes pre-swizzled layout) ----------------
#define WBLOCKS 4096       // KW*CO*CI / 256

__global__ void prep_kernel(const float* __restrict__ wr,
                            const float* __restrict__ wi,
                            const float* __restrict__ ph) {
    int idx = blockIdx.x * 256 + threadIdx.x;
    int i = idx & (CI - 1);
    int o = (idx >> 8) & (CO - 1);
    int k = idx >> 16;
    float s, c;
    sincosf(ph[k], &s, &c);
    int widx = (o * CI + i) * KW + k;            // w_real/w_imag are [o][i][k]
    float v = c * wr[widx] - s * wi[widx];
    int ic = i >> 6;
    int cb = (i & 63) * 2;
    size_t dst = ((size_t)(k * NIC + ic) * CO + o) * 128
               + (uint32_t)(cb ^ ((o & 7) << 4));
    *reinterpret_cast<__half*>(reinterpret_cast<char*>(g_wt) + dst) = __float2half(v);
}

// ---------------- main HMMA kernel ----------------
__global__ __launch_bounds__(256, 2)
void conv_mma_kernel(const float* __restrict__ x, float* __restrict__ out) {
    extern __shared__ char smem[];
    const uint32_t sb = s2u(smem);
    const int tid = threadIdx.x;
    const int l = tid & 31, wid = tid >> 5;
    const int wm = wid & 3, wn = wid >> 2;      // 4(m) x 2(n), warp tile 32x64
    const int t0 = blockIdx.x * MT;
    const int b  = blockIdx.y;
    const int o0 = blockIdx.z * NT;

    const char* gwt = (const char*)g_wt;
    const float* xb = x + (size_t)b * SS * CI;

    float acc[2][8][4];
#pragma unroll
    for (int mt = 0; mt < 2; mt++)
#pragma unroll
        for (int n = 0; n < 8; n++)
#pragma unroll
            for (int q = 0; q < 4; q++) acc[mt][n][q] = 0.f;

    const int lm = l & 15;                          // A row within 16
    const int lg = l >> 4;                          // A k-half
    const int bo_row = (l & 7) + ((l >> 4) << 3);   // B o-row within 16
    const int bhalf = (l >> 3) & 1;                 // B k-half
    const uint32_t rxb = (uint32_t)(l & 7) << 4;    // B swizzle term

    if (tid == 0) {
        mbar_init(MB_B(0)); mbar_init(MB_B(1)); mbar_init(MB_B(2)); mbar_init(MB_B(3));
    }
    // ---- prologue: convert A chunk 0 (all threads), B bulks j=0,1 ----
#pragma unroll
    for (int q = 0; q < 9; q++) {
        int u = q * 256 + tid;
        if (u < AUNITS) conv_A_unit(sb + A_OFF, xb, t0, 0, u);
    }
    __syncthreads();                 // also orders mbar_init before bulk arrivals
    if (tid == 0) {
#pragma unroll
        for (int j = 0; j < 2; j++) {              // B tiles 0,1 (ic=0, k=j)
            mbar_expect(MB_B(j), B_BYTES);
            bulk_g2s(sb + B_OFF + (uint32_t)j * BSTG,
                     gwt + ((size_t)(j * NIC) * CO + o0) * 128, B_BYTES, MB_B(j));
        }
    }

    // compute one flat iteration j against B stage `bstg`
    auto compute_iter = [&](int j, uint32_t abuf, uint32_t bstg) {
        const int k = j & 15;
        const int ra0 = k + wm * 32 + lm;
        const uint32_t rxa = (uint32_t)((k + lm) & 7) << 4;
        const uint32_t rb0 = (uint32_t)(wn * 64 + bo_row) * 128;
#pragma unroll
        for (int ks = 0; ks < 4; ks++) {
            const uint32_t cba = ((uint32_t)(lg * 16 + ks * 32)) ^ rxa;
            const uint32_t cbb = ((uint32_t)(bhalf * 16 + ks * 32)) ^ rxb;
            uint32_t ah[2][4];
#pragma unroll
            for (int mt = 0; mt < 2; mt++)
                ldm_x4(ah[mt], abuf + (uint32_t)(ra0 + mt * 16) * 128 + cba);
#pragma unroll
            for (int p = 0; p < 4; p++) {
                uint32_t bh[4];
                ldm_x4(bh, bstg + rb0 + (uint32_t)(p * 16) * 128 + cbb);
#pragma unroll
                for (int half = 0; half < 2; half++) {
                    int n = p * 2 + half;
                    const uint32_t* bhp = &bh[half * 2];
#pragma unroll
                    for (int mt = 0; mt < 2; mt++)
                        mma16816(acc[mt][n], ah[mt], bhp);
                }
            }
        }
    };

    for (int jj = 0; jj < NITER / 2; jj++) {
        const int j0 = jj * 2, j1 = j0 + 1;
        const int ic = j0 >> 4;
        const uint32_t abuf = sb + A_OFF + (uint32_t)(ic & 1) * ABUF;

        mbar_wait(MB_B(j0 & 3), (j0 >> 2) & 1);
        __syncthreads();             // all warps done with previous pair's stages

        if (tid == 0) {
            // prefetch B for j0+2, j0+3 -> stages (j0+2)&3, (j0+3)&3
#pragma unroll
            for (int d = 2; d < 4; d++) {
                int j2 = j0 + d;
                if (j2 < NITER) {
                    int s2 = j2 & 3;
                    mbar_expect(MB_B(s2), B_BYTES);
                    bulk_g2s(sb + B_OFF + (uint32_t)s2 * BSTG,
                             gwt + ((size_t)((j2 & 15) * NIC + (j2 >> 4)) * CO + o0) * 128,
                             B_BYTES, MB_B(s2));
                }
            }
        }

        // in-kernel A conversion for next chunk: 2 parts per pair, jk0 = 2..12
        {
            int jk0 = j0 & 15;
            if (tid < 192 && jk0 >= 2 && jk0 <= 12 && ic + 1 < NIC) {
                uint32_t ab2 = sb + A_OFF + (uint32_t)((ic + 1) & 1) * ABUF;
                int p0 = (jk0 - 2) * 192 + tid;
                if (p0 < AUNITS) conv_A_unit(ab2, xb, t0, ic + 1, p0);
                int p1 = p0 + 192;
                if (p1 < AUNITS) conv_A_unit(ab2, xb, t0, ic + 1, p1);
            }
        }

        compute_iter(j0, abuf, sb + B_OFF + (uint32_t)(j0 & 3) * BSTG);
        mbar_wait(MB_B(j1 & 3), (j1 >> 2) & 1);     // overlapped by j0 compute
        compute_iter(j1, abuf, sb + B_OFF + (uint32_t)(j1 & 3) * BSTG);
    }

    // ---- epilogue: direct register -> gmem ----
    const int lr = l >> 2, lc = l & 3;
#pragma unroll
    for (int mt = 0; mt < 2; mt++) {
        int r0 = t0 + wm * 32 + mt * 16 + lr;
        int r1 = r0 + 8;
#pragma unroll
        for (int n = 0; n < 8; n++) {
            int o = o0 + wn * 64 + n * 8 + lc * 2;
            if (r0 < TOUT) {
                float2 v = make_float2(acc[mt][n][0], acc[mt][n][1]);
                *reinterpret_cast<float2*>(out + ((size_t)b * TOUT + r0) * CO + o) = v;
            }
            if (r1 < TOUT) {
                float2 v = make_float2(acc[mt][n][2], acc[mt][n][3]);
                *reinterpret_cast<float2*>(out + ((size_t)b * TOUT + r1) * CO + o) = v;
            }
        }
    }
}

// ---------------- launch ----------------
extern "C" void kernel_launch(void* const* d_in, const int* in_sizes, int n_in,
                              void* d_out, int out_size) {
    const float* x  = (const float*)d_in[0];
    const float* wr = (const float*)d_in[1];
    const float* wi = (const float*)d_in[2];
    const float* ph = (const float*)d_in[3];
    float* out = (float*)d_out;
    (void)in_sizes; (void)n_in; (void)out_size;

    cudaFuncSetAttribute(conv_mma_kernel,
                         cudaFuncAttributeMaxDynamicSharedMemorySize, SMEM_TOTAL);

    prep_kernel<<<WBLOCKS, 256>>>(wr, wi, ph);

    dim3 grid(SS / MT, NB, CO / NT);   // 16 x 32 x 2 = 1024 CTAs
    conv_mma_kernel<<<grid, 256, SMEM_TOTAL>>>(x, out);
}

// round 14
// speedup vs baseline: 1.0755x; 1.0755x over previous
#include <cuda_runtime.h>
#include <cuda_fp16.h>
#include <cstdint>

#define NB   32
#define SS   2048
#define SPAD 2064
#define CI   256
#define CO   256
#define KW   16
#define TOUT 2033

#define MT   128
#define NT   128
#define ICH  64
#define NIC  (CI / ICH)    // 4
#define NITER (NIC * KW)   // 64
#define AROWS 143

#define ABUF   18432                 // 144 rows * 128B
#define A_OFF  1024
#define B_OFF  (A_OFF + 2 * ABUF)    // 37888
#define BSTG   16384                 // 128 rows * 128B
#define NSTG   4
#define SMEM_TOTAL (B_OFF + NSTG * BSTG)   // 103424

#define A_BYTES (AROWS * 128)        // 18304
#define B_BYTES (128 * 128)          // 16384

// mbarriers in smem: B stages at +0..+24 ; A bufs at +32,+40
#define MB_B(s) (sb + 8u * (uint32_t)(s))
#define MB_A(p) (sb + 32u + 8u * (uint32_t)(p))

// ---------------- device scratch (pre-swizzled, tile-contiguous) ----------------
__device__ __half g_xt[(size_t)NB * NIC * SPAD * 64];   // [b][ic][t][row 128B, SW128]
__device__ __half g_wt[(size_t)KW * NIC * CO * 64];     // [k][ic][o][row 128B, SW128]

// ---------------- helpers ----------------
__device__ __forceinline__ uint32_t s2u(const void* p) {
    uint32_t a;
    asm("{ .reg .u64 t; cvta.to.shared.u64 t, %1; cvt.u32.u64 %0, t; }"
        : "=r"(a) : "l"(p));
    return a;
}
__device__ __forceinline__ void mbar_init(uint32_t a) {
    asm volatile("mbarrier.init.shared.b64 [%0], 1;" :: "r"(a) : "memory");
}
__device__ __forceinline__ void mbar_expect(uint32_t a, uint32_t bytes) {
    asm volatile("mbarrier.arrive.expect_tx.shared.b64 _, [%0], %1;"
                 :: "r"(a), "r"(bytes) : "memory");
}
__device__ __forceinline__ void bulk_g2s(uint32_t dst, const void* src,
                                         uint32_t bytes, uint32_t mbar) {
    asm volatile(
        "cp.async.bulk.shared::cluster.global.mbarrier::complete_tx::bytes "
        "[%0], [%1], %2, [%3];"
        :: "r"(dst), "l"(src), "r"(bytes), "r"(mbar) : "memory");
}
__device__ __forceinline__ void mbar_wait(uint32_t a, uint32_t parity) {
    asm volatile(
        "{\n\t.reg .pred P;\n\t"
        "WL_%=:\n\t"
        "mbarrier.try_wait.parity.acquire.cta.shared::cta.b64 P, [%0], %1, 0x989680;\n\t"
        "@P bra.uni WD_%=;\n\t"
        "bra.uni WL_%=;\n\t"
        "WD_%=:\n\t}"
        :: "r"(a), "r"(parity) : "memory");
}
__device__ __forceinline__ void ldm_x4(uint32_t* r, uint32_t a) {
    asm volatile("ldmatrix.sync.aligned.m8n8.x4.shared.b16 {%0,%1,%2,%3}, [%4];"
                 : "=r"(r[0]), "=r"(r[1]), "=r"(r[2]), "=r"(r[3]) : "r"(a));
}
__device__ __forceinline__ void mma16816(float* c, const uint32_t* a, const uint32_t* b) {
    asm volatile(
        "mma.sync.aligned.m16n8k16.row.col.f32.f16.f16.f32 "
        "{%0,%1,%2,%3}, {%4,%5,%6,%7}, {%8,%9}, {%0,%1,%2,%3};"
        : "+f"(c[0]), "+f"(c[1]), "+f"(c[2]), "+f"(c[3])
        : "r"(a[0]), "r"(a[1]), "r"(a[2]), "r"(a[3]), "r"(b[0]), "r"(b[1]));
}

// ---------------- fused prep kernel (writes pre-swizzled layouts) ----------------
#define XBLOCKS 8256       // NB*SPAD*CI/8 / 256
#define WBLOCKS 4096       // KW*CO*CI / 256

__global__ void prep_kernel(const float* __restrict__ x,
                            const float* __restrict__ wr,
                            const float* __restrict__ wi,
                            const float* __restrict__ ph) {
    if (blockIdx.x < XBLOCKS) {
        // 8 channels (two float4 loads) per thread -> one uint4 swizzled store
        size_t idx8 = (size_t)blockIdx.x * 256 + threadIdx.x;
        size_t idx = idx8 * 8;
        int i = idx & (CI - 1);                      // multiple of 8
        size_t r = idx >> 8;
        int t = (int)(r % SPAD);
        int b = (int)(r / SPAD);
        float4 v0 = make_float4(0.f, 0.f, 0.f, 0.f);
        float4 v1 = v0;
        if (t < SS) {
            const float4* src = reinterpret_cast<const float4*>(
                x + ((size_t)b * SS + t) * CI + i);
            v0 = src[0];
            v1 = src[1];
        }
        __half2 h0(__float2half(v0.x), __float2half(v0.y));
        __half2 h1(__float2half(v0.z), __float2half(v0.w));
        __half2 h2(__float2half(v1.x), __float2half(v1.y));
        __half2 h3(__float2half(v1.z), __float2half(v1.w));
        int ic = i >> 6;
        uint32_t cb = (uint32_t)((i & 63) * 2);      // 16B-aligned (i % 8 == 0)
        size_t dst = ((size_t)(b * NIC + ic) * SPAD + t) * 128
                   + (cb ^ (((uint32_t)t & 7) << 4));
        uint4 u;
        u.x = *reinterpret_cast<uint32_t*>(&h0);
        u.y = *reinterpret_cast<uint32_t*>(&h1);
        u.z = *reinterpret_cast<uint32_t*>(&h2);
        u.w = *reinterpret_cast<uint32_t*>(&h3);
        *reinterpret_cast<uint4*>(reinterpret_cast<char*>(g_xt) + dst) = u;
    } else {
        int idx = (blockIdx.x - XBLOCKS) * 256 + threadIdx.x;
        int i = idx & (CI - 1);
        int o = (idx >> 8) & (CO - 1);
        int k = idx >> 16;
        float s, c;
        sincosf(ph[k], &s, &c);
        int widx = (o * CI + i) * KW + k;            // w_real/w_imag are [o][i][k]
        float v = c * wr[widx] - s * wi[widx];
        int ic = i >> 6;
        int cb = (i & 63) * 2;
        size_t dst = ((size_t)(k * NIC + ic) * CO + o) * 128
                   + (uint32_t)(cb ^ ((o & 7) << 4));
        *reinterpret_cast<__half*>(reinterpret_cast<char*>(g_wt) + dst) = __float2half(v);
    }
}

// ---------------- main HMMA kernel (round-12 structure) ----------------
__global__ __launch_bounds__(256, 2)
void conv_mma_kernel(float* __restrict__ out) {
    extern __shared__ char smem[];
    const uint32_t sb = s2u(smem);
    const int tid = threadIdx.x;
    const int l = tid & 31, wid = tid >> 5;
    const int wm = wid & 3, wn = wid >> 2;      // 4(m) x 2(n), warp tile 32x64
    const int t0 = blockIdx.x * MT;
    const int b  = blockIdx.y;
    const int o0 = blockIdx.z * NT;

    const char* gxt = (const char*)g_xt;
    const char* gwt = (const char*)g_wt;

    float acc[2][8][4];
#pragma unroll
    for (int mt = 0; mt < 2; mt++)
#pragma unroll
        for (int n = 0; n < 8; n++)
#pragma unroll
            for (int q = 0; q < 4; q++) acc[mt][n][q] = 0.f;

    const int lm = l & 15;                          // A row within 16
    const int lg = l >> 4;                          // A k-half
    const int bo_row = (l & 7) + ((l >> 4) << 3);   // B o-row within 16
    const int bhalf = (l >> 3) & 1;                 // B k-half
    const uint32_t rxb = (uint32_t)(l & 7) << 4;    // B swizzle term

    if (tid == 0) {
        mbar_init(MB_B(0)); mbar_init(MB_B(1)); mbar_init(MB_B(2)); mbar_init(MB_B(3));
        mbar_init(MB_A(0)); mbar_init(MB_A(1));
    }
    __syncthreads();
    if (tid == 0) {
        mbar_expect(MB_A(0), A_BYTES);
        bulk_g2s(sb + A_OFF,
                 gxt + ((size_t)(b * NIC + 0) * SPAD + t0) * 128, A_BYTES, MB_A(0));
#pragma unroll
        for (int j = 0; j < 2; j++) {              // B tiles 0,1 (ic=0, k=j)
            mbar_expect(MB_B(j), B_BYTES);
            bulk_g2s(sb + B_OFF + (uint32_t)j * BSTG,
                     gwt + ((size_t)(j * NIC) * CO + o0) * 128, B_BYTES, MB_B(j));
        }
    }

    // compute one flat iteration j against B stage `bstg`
    auto compute_iter = [&](int j, uint32_t abuf, uint32_t bstg) {
        const int k = j & 15;
        const int ra0 = k + wm * 32 + lm;
        const uint32_t rxa = (uint32_t)((k + lm) & 7) << 4;
        const uint32_t rb0 = (uint32_t)(wn * 64 + bo_row) * 128;
#pragma unroll
        for (int ks = 0; ks < 4; ks++) {
            const uint32_t cba = ((uint32_t)(lg * 16 + ks * 32)) ^ rxa;
            const uint32_t cbb = ((uint32_t)(bhalf * 16 + ks * 32)) ^ rxb;
            uint32_t ah[2][4];
#pragma unroll
            for (int mt = 0; mt < 2; mt++)
                ldm_x4(ah[mt], abuf + (uint32_t)(ra0 + mt * 16) * 128 + cba);
#pragma unroll
            for (int p = 0; p < 4; p++) {
                uint32_t bh[4];
                ldm_x4(bh, bstg + rb0 + (uint32_t)(p * 16) * 128 + cbb);
#pragma unroll
                for (int half = 0; half < 2; half++) {
                    int n = p * 2 + half;
                    const uint32_t* bhp = &bh[half * 2];
#pragma unroll
                    for (int mt = 0; mt < 2; mt++)
                        mma16816(acc[mt][n], ah[mt], bhp);
                }
            }
        }
    };

    for (int jj = 0; jj < NITER / 2; jj++) {
        const int j0 = jj * 2, j1 = j0 + 1;
        const int ic = j0 >> 4;
        const uint32_t abuf = sb + A_OFF + (uint32_t)(ic & 1) * ABUF;

        if ((j0 & 15) == 0) mbar_wait(MB_A(ic & 1), (ic >> 1) & 1);
        mbar_wait(MB_B(j0 & 3), (j0 >> 2) & 1);
        __syncthreads();             // all warps done with previous pair's stages

        if (tid == 0) {
            // prefetch B for j0+2, j0+3 -> stages (j0+2)&3, (j0+3)&3
#pragma unroll
            for (int d = 2; d < 4; d++) {
                int j2 = j0 + d;
                if (j2 < NITER) {
                    int s2 = j2 & 3;
                    mbar_expect(MB_B(s2), B_BYTES);
                    bulk_g2s(sb + B_OFF + (uint32_t)s2 * BSTG,
                             gwt + ((size_t)((j2 & 15) * NIC + (j2 >> 4)) * CO + o0) * 128,
                             B_BYTES, MB_B(s2));
                }
            }
            if ((j0 & 15) == 4 && ic + 1 < NIC) {
                int icn = ic + 1;
                mbar_expect(MB_A(icn & 1), A_BYTES);
                bulk_g2s(sb + A_OFF + (uint32_t)(icn & 1) * ABUF,
                         gxt + ((size_t)(b * NIC + icn) * SPAD + t0) * 128,
                         A_BYTES, MB_A(icn & 1));
            }
        }

        compute_iter(j0, abuf, sb + B_OFF + (uint32_t)(j0 & 3) * BSTG);
        mbar_wait(MB_B(j1 & 3), (j1 >> 2) & 1);     // overlapped by j0 compute
        compute_iter(j1, abuf, sb + B_OFF + (uint32_t)(j1 & 3) * BSTG);
    }

    // ---- epilogue: direct register -> gmem ----
    const int lr = l >> 2, lc = l & 3;
#pragma unroll
    for (int mt = 0; mt < 2; mt++) {
        int r0 = t0 + wm * 32 + mt * 16 + lr;
        int r1 = r0 + 8;
#pragma unroll
        for (int n = 0; n < 8; n++) {
            int o = o0 + wn * 64 + n * 8 + lc * 2;
            if (r0 < TOUT) {
                float2 v = make_float2(acc[mt][n][0], acc[mt][n][1]);
                *reinterpret_cast<float2*>(out + ((size_t)b * TOUT + r0) * CO + o) = v;
            }
            if (r1 < TOUT) {
                float2 v = make_float2(acc[mt][n][2], acc[mt][n][3]);
                *reinterpret_cast<float2*>(out + ((size_t)b * TOUT + r1) * CO + o) = v;
            }
        }
    }
}

// ---------------- launch ----------------
extern "C" void kernel_launch(void* const* d_in, const int* in_sizes, int n_in,
                              void* d_out, int out_size) {
    const float* x  = (const float*)d_in[0];
    const float* wr = (const float*)d_in[1];
    const float* wi = (const float*)d_in[2];
    const float* ph = (const float*)d_in[3];
    float* out = (float*)d_out;
    (void)in_sizes; (void)n_in; (void)out_size;

    cudaFuncSetAttribute(conv_mma_kernel,
                         cudaFuncAttributeMaxDynamicSharedMemorySize, SMEM_TOTAL);

    prep_kernel<<<XBLOCKS + WBLOCKS, 256>>>(x, wr, wi, ph);

    dim3 grid(SS / MT, NB, CO / NT);   // 16 x 32 x 2 = 1024 CTAs
    conv_mma_kernel<<<grid, 256, SMEM_TOTAL>>>(out);
}